// round 2
// baseline (speedup 1.0000x reference)
#include <cuda_runtime.h>
#include <cuda_bf16.h>
#include <cstdint>

#define B_ 4
#define T_ 2048
#define H_ 2048
#define F_ 8192
#define M_ (B_*T_)   // 8192 tokens

// ---------------- device scratch (static; no allocations) ----------------
__device__ __nv_bfloat16 g_wkq[(size_t)F_*H_];   // ternary key weight codes
__device__ __nv_bfloat16 g_wrq[(size_t)H_*H_];   // ternary receptance weight codes
__device__ __nv_bfloat16 g_wvq[(size_t)H_*F_];   // ternary value weight codes
__device__ __nv_bfloat16 g_aK[(size_t)M_*H_];    // int8 codes of key_in (as bf16)
__device__ __nv_bfloat16 g_aR[(size_t)M_*H_];    // int8 codes of rec_in
__device__ __nv_bfloat16 g_aV[(size_t)M_*F_];    // int8 codes of k
__device__ float g_kraw[(size_t)M_*F_];          // k = relu(.)^2, fp32
__device__ float g_rbuf[(size_t)M_*H_];          // sigmoid(receptance)
__device__ float g_sK[M_], g_sR[M_], g_sV[M_];   // per-row dequant scale = clip(amax,1e-5)/127
__device__ float g_part[3*1024];
__device__ float g_ws[6];                        // [2i]=ws, [2i+1]=1/ws  (0=key,1=rec,2=val)

// ---------------- small helpers ----------------
__device__ __forceinline__ float warpSum(float v){
  #pragma unroll
  for(int o=16;o;o>>=1) v += __shfl_xor_sync(0xffffffffu, v, o);
  return v;
}
__device__ __forceinline__ float warpMax(float v){
  #pragma unroll
  for(int o=16;o;o>>=1) v = fmaxf(v, __shfl_xor_sync(0xffffffffu, v, o));
  return v;
}
__device__ __forceinline__ float blkSum(float v, float* sm){
  int t = threadIdx.x, nw = blockDim.x >> 5;
  v = warpSum(v);
  if((t&31)==0) sm[t>>5] = v;
  __syncthreads();
  float r = (t < nw) ? sm[t] : 0.f;
  r = warpSum(r);
  if(t==0) sm[0] = r;
  __syncthreads();
  r = sm[0];
  __syncthreads();
  return r;
}
__device__ __forceinline__ float blkMax(float v, float* sm){
  int t = threadIdx.x, nw = blockDim.x >> 5;
  v = warpMax(v);
  if((t&31)==0) sm[t>>5] = v;
  __syncthreads();
  float r = (t < nw) ? sm[t] : 0.f;
  r = warpMax(r);
  if(t==0) sm[0] = r;
  __syncthreads();
  r = sm[0];
  __syncthreads();
  return r;
}

// ---------------- weight scale: two-stage deterministic mean(|w|) ----------------
__global__ void k_absum(const float* __restrict__ w, int n4, int poff){
  __shared__ float sm[32];
  float s = 0.f;
  const float4* w4 = (const float4*)w;
  for(int i = blockIdx.x*blockDim.x + threadIdx.x; i < n4; i += gridDim.x*blockDim.x){
    float4 v = w4[i];
    s += fabsf(v.x) + fabsf(v.y) + fabsf(v.z) + fabsf(v.w);
  }
  s = blkSum(s, sm);
  if(threadIdx.x == 0) g_part[poff + blockIdx.x] = s;
}

__global__ void k_wsfin(){
  __shared__ float sm[32];
  const float cnts[3] = {(float)((size_t)F_*H_), (float)((size_t)H_*H_), (float)((size_t)H_*F_)};
  for(int i=0;i<3;i++){
    float v = g_part[i*1024 + threadIdx.x];
    float tot = blkSum(v, sm);
    if(threadIdx.x == 0){
      float mean = tot / cnts[i];
      float c = fmaxf(mean, 1e-5f);
      g_ws[2*i]   = 1.f/c;   // ws
      g_ws[2*i+1] = c;       // 1/ws (dequant)
    }
    __syncthreads();
  }
}

// ---------------- ternary weight quantization ----------------
__global__ void k_quantw(const float* __restrict__ w, __nv_bfloat16* __restrict__ wq,
                         int n4, int wsidx){
  float ws = g_ws[2*wsidx];
  for(int i = blockIdx.x*blockDim.x + threadIdx.x; i < n4; i += gridDim.x*blockDim.x){
    float4 v = ((const float4*)w)[i];
    float q0 = fminf(fmaxf(rintf(v.x*ws), -1.f), 1.f);
    float q1 = fminf(fmaxf(rintf(v.y*ws), -1.f), 1.f);
    float q2 = fminf(fmaxf(rintf(v.z*ws), -1.f), 1.f);
    float q3 = fminf(fmaxf(rintf(v.w*ws), -1.f), 1.f);
    __nv_bfloat162* o = ((__nv_bfloat162*)wq) + 2*(size_t)i;
    o[0] = __floats2bfloat162_rn(q0, q1);
    o[1] = __floats2bfloat162_rn(q2, q3);
  }
}

// ---------------- token shift + RMSNorm + int8 activation quant ----------------
__global__ void k_actprep(const float* __restrict__ hidden,
                          const float* __restrict__ tmk, const float* __restrict__ tmr,
                          const float* __restrict__ nk,  const float* __restrict__ nr){
  __shared__ float sm[32];
  int m = blockIdx.x;
  int t = m & (T_-1);
  const float* cur = hidden + (size_t)m*H_;
  float kin[8], rin[8];
  float ssk=0.f, ssr=0.f, amk=0.f, amr=0.f;
  #pragma unroll
  for(int j=0;j<8;j++){
    int h = threadIdx.x + j*256;
    float xc = cur[h];
    float xp = (t==0) ? 0.f : cur[h - H_];
    float a = tmk[h], b = tmr[h];
    float ki = xc*a + xp*(1.f-a);
    float ri = xc*b + xp*(1.f-b);
    kin[j]=ki; rin[j]=ri;
    ssk += ki*ki; ssr += ri*ri;
    amk = fmaxf(amk, fabsf(ki*nk[h]));
    amr = fmaxf(amr, fabsf(ri*nr[h]));
  }
  float tssk = blkSum(ssk, sm);
  float tssr = blkSum(ssr, sm);
  float tamk = blkMax(amk, sm);
  float tamr = blkMax(amr, sm);
  float rk = rsqrtf(tssk*(1.f/H_) + 1e-8f);
  float rr = rsqrtf(tssr*(1.f/H_) + 1e-8f);
  float rsK = fmaxf(tamk*rk, 1e-5f);
  float rsR = fmaxf(tamr*rr, 1e-5f);
  float sk = 127.f/rsK, sr = 127.f/rsR;
  #pragma unroll
  for(int j=0;j<8;j++){
    int h = threadIdx.x + j*256;
    float qk = fminf(fmaxf(rintf(kin[j]*nk[h]*rk*sk), -128.f), 127.f);
    float qr = fminf(fmaxf(rintf(rin[j]*nr[h]*rr*sr), -128.f), 127.f);
    g_aK[(size_t)m*H_ + h] = __float2bfloat16(qk);
    g_aR[(size_t)m*H_ + h] = __float2bfloat16(qr);
  }
  if(threadIdx.x == 0){ g_sK[m] = rsK*(1.f/127.f); g_sR[m] = rsR*(1.f/127.f); }
}

// ---------------- RMSNorm + int8 quant of k rows (F=8192) ----------------
__global__ void k_quantK(const float* __restrict__ nv){
  __shared__ float sm[32];
  int m = blockIdx.x;
  const float* row = g_kraw + (size_t)m*F_;
  float v[32];
  float ss=0.f, am=0.f;
  #pragma unroll
  for(int j=0;j<32;j++){
    int h = threadIdx.x + j*256;
    float x = row[h];
    v[j] = x;
    ss += x*x;
    am = fmaxf(am, fabsf(x*nv[h]));
  }
  float tss = blkSum(ss, sm);
  float tam = blkMax(am, sm);
  float rinv = rsqrtf(tss*(1.f/F_) + 1e-8f);
  float rs = fmaxf(tam*rinv, 1e-5f);
  float s = 127.f/rs;
  #pragma unroll
  for(int j=0;j<32;j++){
    int h = threadIdx.x + j*256;
    float q = fminf(fmaxf(rintf(v[j]*nv[h]*rinv*s), -128.f), 127.f);
    g_aV[(size_t)m*F_ + h] = __float2bfloat16(q);
  }
  if(threadIdx.x == 0) g_sV[m] = rs*(1.f/127.f);
}

// ---------------- bf16 tensor-core GEMM: C[M,N] = A[M,K] * Bw[N,K]^T ----------------
#define BM 128
#define BN 128
#define BKg 32
#define LDT 40   // BKg + 8 pad -> 80B row stride, conflict-free fragment LDS

__device__ __forceinline__ void cp16(uint32_t s, const void* g){
  asm volatile("cp.async.cg.shared.global [%0], [%1], 16;\n" :: "r"(s), "l"(g));
}
__device__ __forceinline__ void mma16816(float* c, const uint32_t* a, const uint32_t* b){
  asm volatile(
    "mma.sync.aligned.m16n8k16.row.col.f32.bf16.bf16.f32 "
    "{%0,%1,%2,%3}, {%4,%5,%6,%7}, {%8,%9}, {%0,%1,%2,%3};\n"
    : "+f"(c[0]), "+f"(c[1]), "+f"(c[2]), "+f"(c[3])
    : "r"(a[0]), "r"(a[1]), "r"(a[2]), "r"(a[3]), "r"(b[0]), "r"(b[1]));
}

// MODE 0: key   -> g_kraw = relu(x)^2
// MODE 1: rec   -> g_rbuf = sigmoid(x)
// MODE 2: value -> Cout   = x * g_rbuf
template<int MODE>
__global__ __launch_bounds__(256) void k_gemm(float* __restrict__ Cout){
  constexpr int Ndim = (MODE==0) ? F_ : H_;
  constexpr int Kdim = (MODE==2) ? F_ : H_;
  const __nv_bfloat16* __restrict__ A  = (MODE==0) ? g_aK  : (MODE==1) ? g_aR  : g_aV;
  const __nv_bfloat16* __restrict__ Bw = (MODE==0) ? g_wkq : (MODE==1) ? g_wrq : g_wvq;
  const float* __restrict__ rowscale   = (MODE==0) ? g_sK  : (MODE==1) ? g_sR  : g_sV;
  float* __restrict__ C                = (MODE==0) ? g_kraw : (MODE==1) ? g_rbuf : Cout;
  const float wdeq = g_ws[2*((MODE==0)?0:(MODE==1)?1:2) + 1];

  __shared__ __nv_bfloat16 sA[2][BM*LDT];
  __shared__ __nv_bfloat16 sB[2][BN*LDT];

  const int tid = threadIdx.x;
  const int bm = blockIdx.y*BM, bn = blockIdx.x*BN;

  auto issue = [&](int buf, int kt){
    int k0 = kt*BKg;
    #pragma unroll
    for(int i=0;i<2;i++){
      int chunk = tid + 256*i;              // 0..511 : 128 rows x 4 x 16B
      int row = chunk >> 2;
      int kc  = (chunk & 3) << 3;           // 0,8,16,24 elems
      cp16((uint32_t)__cvta_generic_to_shared(&sA[buf][row*LDT + kc]),
           A  + (size_t)(bm+row)*Kdim + k0 + kc);
      cp16((uint32_t)__cvta_generic_to_shared(&sB[buf][row*LDT + kc]),
           Bw + (size_t)(bn+row)*Kdim + k0 + kc);
    }
    asm volatile("cp.async.commit_group;\n" ::: "memory");
  };

  const int warp = tid >> 5, lane = tid & 31;
  const int wm = (warp >> 2) * 64;   // 2 warps in M
  const int wn = (warp & 3) * 32;    // 4 warps in N
  const int g = lane >> 2, q = lane & 3;

  float acc[4][4][4];
  #pragma unroll
  for(int a0=0;a0<4;a0++)
    #pragma unroll
    for(int b0=0;b0<4;b0++)
      #pragma unroll
      for(int c0=0;c0<4;c0++) acc[a0][b0][c0]=0.f;

  constexpr int nkt = Kdim / BKg;
  issue(0, 0);
  #pragma unroll 1
  for(int kt=0; kt<nkt; kt++){
    int buf = kt & 1;
    if(kt+1 < nkt){
      issue(buf^1, kt+1);
      asm volatile("cp.async.wait_group 1;\n" ::: "memory");
    } else {
      asm volatile("cp.async.wait_group 0;\n" ::: "memory");
    }
    __syncthreads();

    #pragma unroll
    for(int ks=0; ks<2; ks++){
      const int kk = ks*16;
      uint32_t afr[4][4], bfr[4][2];
      #pragma unroll
      for(int mi=0; mi<4; mi++){
        const __nv_bfloat16* base = &sA[buf][(wm + mi*16 + g)*LDT + kk + 2*q];
        afr[mi][0] = *(const uint32_t*)(base);
        afr[mi][1] = *(const uint32_t*)(base + 8*LDT);
        afr[mi][2] = *(const uint32_t*)(base + 8);
        afr[mi][3] = *(const uint32_t*)(base + 8*LDT + 8);
      }
      #pragma unroll
      for(int ni=0; ni<4; ni++){
        const __nv_bfloat16* base = &sB[buf][(wn + ni*8 + g)*LDT + kk + 2*q];
        bfr[ni][0] = *(const uint32_t*)(base);
        bfr[ni][1] = *(const uint32_t*)(base + 8);
      }
      #pragma unroll
      for(int mi=0; mi<4; mi++)
        #pragma unroll
        for(int ni=0; ni<4; ni++)
          mma16816(acc[mi][ni], afr[mi], bfr[ni]);
    }
    __syncthreads();
  }

  // epilogue
  #pragma unroll
  for(int mi=0; mi<4; mi++){
    int r0 = bm + wm + mi*16 + g;
    int r1 = r0 + 8;
    float sc0 = rowscale[r0]*wdeq;
    float sc1 = rowscale[r1]*wdeq;
    #pragma unroll
    for(int ni=0; ni<4; ni++){
      int col = bn + wn + ni*8 + 2*q;
      float x0 = acc[mi][ni][0]*sc0, x1 = acc[mi][ni][1]*sc0;
      float x2 = acc[mi][ni][2]*sc1, x3 = acc[mi][ni][3]*sc1;
      if(MODE == 0){
        x0 = (x0>0.f)? x0*x0 : 0.f;  x1 = (x1>0.f)? x1*x1 : 0.f;
        x2 = (x2>0.f)? x2*x2 : 0.f;  x3 = (x3>0.f)? x3*x3 : 0.f;
      } else if(MODE == 1){
        x0 = 1.f/(1.f+expf(-x0)); x1 = 1.f/(1.f+expf(-x1));
        x2 = 1.f/(1.f+expf(-x2)); x3 = 1.f/(1.f+expf(-x3));
      } else {
        float2 m0 = *(const float2*)&g_rbuf[(size_t)r0*Ndim + col];
        float2 m1 = *(const float2*)&g_rbuf[(size_t)r1*Ndim + col];
        x0 *= m0.x; x1 *= m0.y; x2 *= m1.x; x3 *= m1.y;
      }
      *(float2*)&C[(size_t)r0*Ndim + col] = make_float2(x0, x1);
      *(float2*)&C[(size_t)r1*Ndim + col] = make_float2(x2, x3);
    }
  }
}

// ---------------- launch ----------------
extern "C" void kernel_launch(void* const* d_in, const int* in_sizes, int n_in,
                              void* d_out, int out_size){
  const float* hidden = (const float*)d_in[0];
  const float* tmk    = (const float*)d_in[1];
  const float* tmr    = (const float*)d_in[2];
  const float* w_key  = (const float*)d_in[3];
  const float* w_rec  = (const float*)d_in[4];
  const float* w_val  = (const float*)d_in[5];
  const float* nk     = (const float*)d_in[6];
  const float* nr     = (const float*)d_in[7];
  const float* nv     = (const float*)d_in[8];
  float* out = (float*)d_out;

  __nv_bfloat16 *wkq, *wrq, *wvq;
  cudaGetSymbolAddress((void**)&wkq, g_wkq);
  cudaGetSymbolAddress((void**)&wrq, g_wrq);
  cudaGetSymbolAddress((void**)&wvq, g_wvq);

  // 1) weight scales
  k_absum<<<1024,256>>>(w_key, (F_*H_)/4, 0);
  k_absum<<<1024,256>>>(w_rec, (H_*H_)/4, 1024);
  k_absum<<<1024,256>>>(w_val, (H_*F_)/4, 2048);
  k_wsfin<<<1,1024>>>();

  // 2) ternary weight codes
  k_quantw<<<4096,256>>>(w_key, wkq, (F_*H_)/4, 0);
  k_quantw<<<1024,256>>>(w_rec, wrq, (H_*H_)/4, 1);
  k_quantw<<<4096,256>>>(w_val, wvq, (H_*F_)/4, 2);

  // 3) token-shift mix + RMSNorm + int8 codes for key_in / rec_in
  k_actprep<<<M_,256>>>(hidden, tmk, tmr, nk, nr);

  // 4) key GEMM -> relu^2 -> k (fp32)
  k_gemm<0><<<dim3(F_/BN, M_/BM), 256>>>(nullptr);

  // 5) RMSNorm + int8 codes for k
  k_quantK<<<M_,256>>>(nv);

  // 6) receptance GEMM -> sigmoid -> r
  k_gemm<1><<<dim3(H_/BN, M_/BM), 256>>>(nullptr);

  // 7) value GEMM -> * r -> out
  k_gemm<2><<<dim3(H_/BN, M_/BM), 256>>>(out);
}